// round 14
// baseline (speedup 1.0000x reference)
#include <cuda_runtime.h>
#include <cuda_bf16.h>

#define NN 50000
#define EE 800000
#define HH 64
#define GG 512
#define OO 32
#define SLOT 64   // per-node edge capacity; P(deg>=64)~1e-22 for Poisson(16)

// ---------------- scratch (device globals) ----------------------------------
__device__ __align__(16) float g_xl[NN * HH];
__device__ __align__(16) float g_xr[NN * HH];
__device__ __align__(16) float g_h [NN * HH];
__device__ int g_deg[NN];
__device__ int g_slot[NN * SLOT];
__device__ int g_e64;
__device__ int g_b64;

// ---------------- helpers ----------------------------------------------------
__device__ __forceinline__ long long load_idx(const void* p, long long i, int is64) {
    return is64 ? ((const long long*)p)[i] : (long long)((const int*)p)[i];
}

#define PACK2(d, lo, hi) asm("mov.b64 %0, {%1, %2};" : "=l"(d) : "f"(lo), "f"(hi))
#define UNPACK2(lo, hi, s) asm("mov.b64 {%0, %1}, %2;" : "=f"(lo), "=f"(hi) : "l"(s))
#define FMA2(acc, a, b) asm("fma.rn.f32x2 %0, %1, %2, %0;" : "+l"(acc) : "l"(a), "l"(b))

// score contribution: lrelu(z)*att = 0.4*att*(1.5*z + |z|), c2 = 0.4*att
__device__ __forceinline__ float scoreterm(float a, float xr, float c2, float p) {
    float z = a + xr;
    float u = fmaf(1.5f, z, fabsf(z));
    return fmaf(c2, u, p);
}

// ---------------- dtype detection + deg zero ---------------------------------
__global__ void k_detect(const void* ei, const void* batch) {
    int i = blockIdx.x * blockDim.x + threadIdx.x;
    if (i < NN) g_deg[i] = 0;
    if (i != 0) return;
    const long long* p = (const long long*)ei;
    int ok = 1;
    for (int j = 0; j < 16; j++) { long long v = p[j]; if (v < 0 || v >= NN) ok = 0; }
    g_e64 = ok;
    const int* q = (const int*)batch;
    int zero_high = 1;
    for (int j = 0; j < 16; j++) { if (q[20000 + 2 * j + 1] != 0) zero_high = 0; }
    g_b64 = zero_high;
}

// ---------------- one-pass padded CSR build -----------------------------------
__global__ void k_build(const void* __restrict__ ei) {
    int e = blockIdx.x * blockDim.x + threadIdx.x;
    if (e >= EE) return;
    int is64 = g_e64;
    int s = (int)load_idx(ei, e, is64);
    int d = (int)load_idx(ei, (long long)EE + e, is64);
    int pos = atomicAdd(&g_deg[d], 1);
    if (pos < SLOT) g_slot[(size_t)d * SLOT + pos] = s;
}

// ---------------- dual GEMM: xl = in@Wl+bl, xr = in@Wr+br --------------------
__global__ void __launch_bounds__(256) k_gemm_dual(
        const float* __restrict__ x,
        const float* __restrict__ Wl, const float* __restrict__ bl,
        const float* __restrict__ Wr, const float* __restrict__ br,
        float* __restrict__ xl, float* __restrict__ xr) {
    __shared__ float sX[64 * 64];
    __shared__ float sWl[64 * 64];
    __shared__ float sWr[64 * 64];
    int tid = threadIdx.x;
    int row0 = blockIdx.x * 64;
    for (int i = tid; i < 1024; i += 256) {
        ((float4*)sWl)[i] = ((const float4*)Wl)[i];
        ((float4*)sWr)[i] = ((const float4*)Wr)[i];
    }
    for (int i = tid; i < 1024; i += 256) {
        int r = i >> 4, k4 = (i & 15) << 2;
        float4 v = make_float4(0.f, 0.f, 0.f, 0.f);
        if (row0 + r < NN) v = *(const float4*)(x + (size_t)(row0 + r) * 64 + k4);
        *(float4*)(sX + r * 64 + k4) = v;
    }
    __syncthreads();
    int tx = tid & 15, ty = tid >> 4;
    int r0 = ty * 4, c0 = tx * 4;
    float4 bl4 = *(const float4*)(bl + c0);
    float4 br4 = *(const float4*)(br + c0);
    unsigned long long accl[4][2], accr[4][2];
    {
        const float* blp = (const float*)&bl4;
        const float* brp = (const float*)&br4;
#pragma unroll
        for (int c = 0; c < 4; c++) {
            PACK2(accl[c][0], blp[c], blp[c]); PACK2(accl[c][1], blp[c], blp[c]);
            PACK2(accr[c][0], brp[c], brp[c]); PACK2(accr[c][1], brp[c], brp[c]);
        }
    }
#pragma unroll 4
    for (int k = 0; k < 64; k++) {
        float a0 = sX[(r0 + 0) * 64 + k];
        float a1 = sX[(r0 + 1) * 64 + k];
        float a2 = sX[(r0 + 2) * 64 + k];
        float a3 = sX[(r0 + 3) * 64 + k];
        unsigned long long a01, a23;
        PACK2(a01, a0, a1); PACK2(a23, a2, a3);
        float4 wl = *(const float4*)(sWl + k * 64 + c0);
        float4 wr = *(const float4*)(sWr + k * 64 + c0);
        const float* wlp = (const float*)&wl;
        const float* wrp = (const float*)&wr;
#pragma unroll
        for (int c = 0; c < 4; c++) {
            unsigned long long wd;
            PACK2(wd, wlp[c], wlp[c]);
            FMA2(accl[c][0], a01, wd); FMA2(accl[c][1], a23, wd);
            PACK2(wd, wrp[c], wrp[c]);
            FMA2(accr[c][0], a01, wd); FMA2(accr[c][1], a23, wd);
        }
    }
    float vl[4][4], vr[4][4];
#pragma unroll
    for (int c = 0; c < 4; c++) {
        float lo, hi;
        UNPACK2(lo, hi, accl[c][0]); vl[0][c] = lo; vl[1][c] = hi;
        UNPACK2(lo, hi, accl[c][1]); vl[2][c] = lo; vl[3][c] = hi;
        UNPACK2(lo, hi, accr[c][0]); vr[0][c] = lo; vr[1][c] = hi;
        UNPACK2(lo, hi, accr[c][1]); vr[2][c] = lo; vr[3][c] = hi;
    }
#pragma unroll
    for (int i = 0; i < 4; i++) {
        int row = row0 + r0 + i;
        if (row < NN) {
            *(float4*)(xl + (size_t)row * 64 + c0) = *(float4*)vl[i];
            *(float4*)(xr + (size_t)row * 64 + c0) = *(float4*)vr[i];
        }
    }
}

// ---------------- fused GATv2 edge phase --------------------------------------
// one node per 32-thread block (R12 config — best measured). 2 groups of 16
// lanes; each lane owns 4 features; SOFTWARE-PIPELINED edge loop: the next 8
// edges' rows are prefetched (predicated) before scoring the current 8,
// overlapping the ~260-cycle L2 gather with the compute chain.
__global__ void __launch_bounds__(32) k_gat_node(
        const float* __restrict__ att, const float* __restrict__ bias,
        float* __restrict__ hout) {
    int n = blockIdx.x;
    int lane = threadIdx.x;
    int end = g_deg[n]; if (end > SLOT) end = SLOT;
    const int* srcs = g_slot + (size_t)n * SLOT;
    int sub = lane & 15;      // feature quad: features sub*4 .. sub*4+3
    int grp = lane >> 4;      // edge group 0..1

    float4 xr4 = *(const float4*)(g_xr + (size_t)n * 64 + sub * 4);
    float4 c2  = *(const float4*)(att + sub * 4);
    c2.x *= 0.4f; c2.y *= 0.4f; c2.z *= 0.4f; c2.w *= 0.4f;

    float den = 0.0f;
    float4 acc = make_float4(0.f, 0.f, 0.f, 0.f);
    const float4 z4 = make_float4(0.f, 0.f, 0.f, 0.f);

    for (int base = 0; base < end; base += 32) {
        int cnt = end - base; if (cnt > 32) cnt = 32;
        int sv = (base + lane < end) ? srcs[base + lane] : 0;

        // prologue: load edge group j=0 (predicated)
        int e0 = grp, e1 = 2 + grp, e2 = 4 + grp, e3 = 6 + grp;
        float4 a = z4, b = z4, c = z4, d = z4;
        {
            int s0 = __shfl_sync(0xffffffffu, sv, e0);
            int s1 = __shfl_sync(0xffffffffu, sv, e1);
            int s2 = __shfl_sync(0xffffffffu, sv, e2);
            int s3 = __shfl_sync(0xffffffffu, sv, e3);
            if (e0 < cnt) a = *(const float4*)(g_xl + (size_t)s0 * 64 + sub * 4);
            if (e1 < cnt) b = *(const float4*)(g_xl + (size_t)s1 * 64 + sub * 4);
            if (e2 < cnt) c = *(const float4*)(g_xl + (size_t)s2 * 64 + sub * 4);
            if (e3 < cnt) d = *(const float4*)(g_xl + (size_t)s3 * 64 + sub * 4);
        }

        for (int j = 0; j < cnt; j += 8) {
            // ---- prefetch next 8 edges (issues before the compute chain) ----
            int f0 = j + 8 + grp, f1 = j + 10 + grp, f2 = j + 12 + grp, f3 = j + 14 + grp;
            float4 na = z4, nb = z4, nc = z4, nd = z4;
            if (j + 8 < cnt) {
                int t0 = __shfl_sync(0xffffffffu, sv, f0 & 31);
                int t1 = __shfl_sync(0xffffffffu, sv, f1 & 31);
                int t2 = __shfl_sync(0xffffffffu, sv, f2 & 31);
                int t3 = __shfl_sync(0xffffffffu, sv, f3 & 31);
                if (f0 < cnt) na = *(const float4*)(g_xl + (size_t)t0 * 64 + sub * 4);
                if (f1 < cnt) nb = *(const float4*)(g_xl + (size_t)t1 * 64 + sub * 4);
                if (f2 < cnt) nc = *(const float4*)(g_xl + (size_t)t2 * 64 + sub * 4);
                if (f3 < cnt) nd = *(const float4*)(g_xl + (size_t)t3 * 64 + sub * 4);
            }

            // ---- score + accumulate current 8 edges ----
            float p0 = 0.f, p1 = 0.f, p2 = 0.f, p3 = 0.f;
            p0 = scoreterm(a.x, xr4.x, c2.x, p0);
            p0 = scoreterm(a.y, xr4.y, c2.y, p0);
            p0 = scoreterm(a.z, xr4.z, c2.z, p0);
            p0 = scoreterm(a.w, xr4.w, c2.w, p0);
            p1 = scoreterm(b.x, xr4.x, c2.x, p1);
            p1 = scoreterm(b.y, xr4.y, c2.y, p1);
            p1 = scoreterm(b.z, xr4.z, c2.z, p1);
            p1 = scoreterm(b.w, xr4.w, c2.w, p1);
            p2 = scoreterm(c.x, xr4.x, c2.x, p2);
            p2 = scoreterm(c.y, xr4.y, c2.y, p2);
            p2 = scoreterm(c.z, xr4.z, c2.z, p2);
            p2 = scoreterm(c.w, xr4.w, c2.w, p2);
            p3 = scoreterm(d.x, xr4.x, c2.x, p3);
            p3 = scoreterm(d.y, xr4.y, c2.y, p3);
            p3 = scoreterm(d.z, xr4.z, c2.z, p3);
            p3 = scoreterm(d.w, xr4.w, c2.w, p3);
            p0 += __shfl_xor_sync(0xffffffffu, p0, 1);
            p1 += __shfl_xor_sync(0xffffffffu, p1, 1);
            p2 += __shfl_xor_sync(0xffffffffu, p2, 1);
            p3 += __shfl_xor_sync(0xffffffffu, p3, 1);
            p0 += __shfl_xor_sync(0xffffffffu, p0, 2);
            p1 += __shfl_xor_sync(0xffffffffu, p1, 2);
            p2 += __shfl_xor_sync(0xffffffffu, p2, 2);
            p3 += __shfl_xor_sync(0xffffffffu, p3, 2);
            p0 += __shfl_xor_sync(0xffffffffu, p0, 4);
            p1 += __shfl_xor_sync(0xffffffffu, p1, 4);
            p2 += __shfl_xor_sync(0xffffffffu, p2, 4);
            p3 += __shfl_xor_sync(0xffffffffu, p3, 4);
            p0 += __shfl_xor_sync(0xffffffffu, p0, 8);
            p1 += __shfl_xor_sync(0xffffffffu, p1, 8);
            p2 += __shfl_xor_sync(0xffffffffu, p2, 8);
            p3 += __shfl_xor_sync(0xffffffffu, p3, 8);
            int ce0 = j + grp, ce1 = j + 2 + grp, ce2 = j + 4 + grp, ce3 = j + 6 + grp;
            if (ce0 >= cnt) p0 = -1e30f;
            if (ce1 >= cnt) p1 = -1e30f;
            if (ce2 >= cnt) p2 = -1e30f;
            if (ce3 >= cnt) p3 = -1e30f;
            float w0 = __expf(p0);
            float w1 = __expf(p1);
            float w2 = __expf(p2);
            float w3 = __expf(p3);
            den += (w0 + w1) + (w2 + w3);
            acc.x += w0 * a.x + w1 * b.x + w2 * c.x + w3 * d.x;
            acc.y += w0 * a.y + w1 * b.y + w2 * c.y + w3 * d.y;
            acc.z += w0 * a.z + w1 * b.z + w2 * c.z + w3 * d.z;
            acc.w += w0 * a.w + w1 * b.w + w2 * c.w + w3 * d.w;

            a = na; b = nb; c = nc; d = nd;
        }
    }

    // merge the 2 group partial sums (plain adds)
    den   += __shfl_xor_sync(0xffffffffu, den, 16);
    acc.x += __shfl_xor_sync(0xffffffffu, acc.x, 16);
    acc.y += __shfl_xor_sync(0xffffffffu, acc.y, 16);
    acc.z += __shfl_xor_sync(0xffffffffu, acc.z, 16);
    acc.w += __shfl_xor_sync(0xffffffffu, acc.w, 16);

    if (grp == 0) {
        float inv = den > 0.0f ? 1.0f / den : 0.0f;
        float4 b4 = *(const float4*)(bias + sub * 4);
        float4 o;
        o.x = fmaxf(acc.x * inv + b4.x, 0.f);
        o.y = fmaxf(acc.y * inv + b4.y, 0.f);
        o.z = fmaxf(acc.z * inv + b4.z, 0.f);
        o.w = fmaxf(acc.w * inv + b4.w, 0.f);
        *(float4*)(hout + (size_t)n * 64 + sub * 4) = o;
    }
}

// ---------------- fused mean-pool + final linear -----------------------------
__global__ void __launch_bounds__(256) k_pool_final(
        const void* __restrict__ batch,
        const float* __restrict__ lw, const float* __restrict__ lb,
        float* __restrict__ out) {
    __shared__ float sp[8][64];
    int warp = (blockIdx.x << 3) + (threadIdx.x >> 5);
    int lane = threadIdx.x & 31;
    int wloc = threadIdx.x >> 5;
    if (warp >= GG) return;
    int g = warp;
    int b64 = g_b64;

    int lo = 0, hi = NN;
    while (lo < hi) { int mid = (lo + hi) >> 1; if (load_idx(batch, mid, b64) < (long long)g) lo = mid + 1; else hi = mid; }
    int beg = lo;
    hi = NN;
    while (lo < hi) { int mid = (lo + hi) >> 1; if (load_idx(batch, mid, b64) < (long long)(g + 1)) lo = mid + 1; else hi = mid; }
    int end = lo;

    float sx = 0.f, sy = 0.f;
    const float* hp = g_h + 2 * lane;
    int n = beg;
    for (; n + 4 <= end; n += 4) {
        float2 v0 = *(const float2*)(hp + (size_t)n * 64);
        float2 v1 = *(const float2*)(hp + (size_t)(n + 1) * 64);
        float2 v2 = *(const float2*)(hp + (size_t)(n + 2) * 64);
        float2 v3 = *(const float2*)(hp + (size_t)(n + 3) * 64);
        sx += (v0.x + v1.x) + (v2.x + v3.x);
        sy += (v0.y + v1.y) + (v2.y + v3.y);
    }
    for (; n < end; n++) {
        float2 v = *(const float2*)(hp + (size_t)n * 64);
        sx += v.x; sy += v.y;
    }
    float c = (float)(end - beg);
    c = c > 1.0f ? c : 1.0f;
    sp[wloc][2 * lane]     = sx / c;
    sp[wloc][2 * lane + 1] = sy / c;
    __syncwarp();
    float acc = lb[lane];
#pragma unroll
    for (int hh = 0; hh < 64; hh++) acc = fmaf(sp[wloc][hh], lw[hh * 32 + lane], acc);
    out[g * 32 + lane] = acc;
}

// ---------------- launch ---------------------------------------------------------
extern "C" void kernel_launch(void* const* d_in, const int* in_sizes, int n_in,
                              void* d_out, int out_size) {
    const float* x      = (const float*)d_in[0];
    const void*  ei     = d_in[1];
    const void*  batch  = d_in[2];
    const float* Wl1    = (const float*)d_in[3];
    const float* bl1    = (const float*)d_in[4];
    const float* Wr1    = (const float*)d_in[5];
    const float* br1    = (const float*)d_in[6];
    const float* att1   = (const float*)d_in[7];
    const float* bias1  = (const float*)d_in[8];
    const float* Wl2    = (const float*)d_in[9];
    const float* bl2    = (const float*)d_in[10];
    const float* Wr2    = (const float*)d_in[11];
    const float* br2    = (const float*)d_in[12];
    const float* att2   = (const float*)d_in[13];
    const float* bias2  = (const float*)d_in[14];
    const float* lin_w  = (const float*)d_in[15];
    const float* lin_b  = (const float*)d_in[16];

    float* xl = nullptr; float* xr = nullptr; float* h = nullptr;
    cudaGetSymbolAddress((void**)&xl, g_xl);
    cudaGetSymbolAddress((void**)&xr, g_xr);
    cudaGetSymbolAddress((void**)&h,  g_h);

    // side stream + events for fork/join (created once, outside any capture)
    static cudaStream_t s2 = nullptr;
    static cudaEvent_t evFork = nullptr, evJoin = nullptr;
    if (s2 == nullptr) {
        cudaStreamCreateWithFlags(&s2, cudaStreamNonBlocking);
        cudaEventCreateWithFlags(&evFork, cudaEventDisableTiming);
        cudaEventCreateWithFlags(&evJoin, cudaEventDisableTiming);
    }

    const int TB = 256;
    const int gEdge = (EE + TB - 1) / TB;         // 3125
    const int gNode = (NN + TB - 1) / TB;         // 196
    const int gGemm = (NN + 63) / 64;             // 782

    // fork: gemm1 on s2 runs concurrently with CSR build on the main stream
    cudaEventRecord(evFork, 0);
    cudaStreamWaitEvent(s2, evFork, 0);
    k_gemm_dual<<<gGemm, TB, 0, s2>>>(x, Wl1, bl1, Wr1, br1, xl, xr);
    cudaEventRecord(evJoin, s2);

    // one-pass padded CSR build on the main stream
    k_detect<<<gNode, TB>>>(ei, batch);
    k_build<<<gEdge, TB>>>(ei);

    // join: gat1 needs both CSR and gemm1 results
    cudaStreamWaitEvent(0, evJoin, 0);

    // ---- layer 1 ---- (one node per 32-thread block, pipelined)
    k_gat_node<<<NN, 32>>>(att1, bias1, h);

    // ---- layer 2 ----
    k_gemm_dual<<<gGemm, TB>>>(h, Wl2, bl2, Wr2, br2, xl, xr);
    k_gat_node<<<NN, 32>>>(att2, bias2, h);

    // ---- fused pool + final linear ----
    k_pool_final<<<(GG + 7) / 8, TB>>>(batch, lin_w, lin_b, (float*)d_out);
}

// round 15
// speedup vs baseline: 1.0250x; 1.0250x over previous
#include <cuda_runtime.h>
#include <cuda_bf16.h>

#define NN 50000
#define EE 800000
#define HH 64
#define GG 512
#define OO 32
#define SLOT 64   // per-node edge capacity; P(deg>=64)~1e-22 for Poisson(16)

// ---------------- scratch (device globals) ----------------------------------
__device__ __align__(16) float g_xl[NN * HH];
__device__ __align__(16) float g_xr[NN * HH];
__device__ __align__(16) float g_h [NN * HH];
__device__ int g_deg[NN];
__device__ int g_slot[NN * SLOT];
__device__ int g_e64;
__device__ int g_b64;

// ---------------- helpers ----------------------------------------------------
__device__ __forceinline__ long long load_idx(const void* p, long long i, int is64) {
    return is64 ? ((const long long*)p)[i] : (long long)((const int*)p)[i];
}

#define PACK2(d, lo, hi) asm("mov.b64 %0, {%1, %2};" : "=l"(d) : "f"(lo), "f"(hi))
#define UNPACK2(lo, hi, s) asm("mov.b64 {%0, %1}, %2;" : "=f"(lo), "=f"(hi) : "l"(s))
#define FMA2(acc, a, b) asm("fma.rn.f32x2 %0, %1, %2, %0;" : "+l"(acc) : "l"(a), "l"(b))

// score contribution: lrelu(z)*att = 0.4*att*(1.5*z + |z|), c2 = 0.4*att
__device__ __forceinline__ float scoreterm(float a, float xr, float c2, float p) {
    float z = a + xr;
    float u = fmaf(1.5f, z, fabsf(z));
    return fmaf(c2, u, p);
}

// ---------------- dtype detection + deg zero ---------------------------------
__global__ void k_detect(const void* ei, const void* batch) {
    int i = blockIdx.x * blockDim.x + threadIdx.x;
    if (i < NN) g_deg[i] = 0;
    if (i != 0) return;
    const long long* p = (const long long*)ei;
    int ok = 1;
    for (int j = 0; j < 16; j++) { long long v = p[j]; if (v < 0 || v >= NN) ok = 0; }
    g_e64 = ok;
    const int* q = (const int*)batch;
    int zero_high = 1;
    for (int j = 0; j < 16; j++) { if (q[20000 + 2 * j + 1] != 0) zero_high = 0; }
    g_b64 = zero_high;
}

// ---------------- one-pass padded CSR build -----------------------------------
__global__ void k_build(const void* __restrict__ ei) {
    int e = blockIdx.x * blockDim.x + threadIdx.x;
    if (e >= EE) return;
    int is64 = g_e64;
    int s = (int)load_idx(ei, e, is64);
    int d = (int)load_idx(ei, (long long)EE + e, is64);
    int pos = atomicAdd(&g_deg[d], 1);
    if (pos < SLOT) g_slot[(size_t)d * SLOT + pos] = s;
}

// ---------------- dual GEMM: xl = in@Wl+bl, xr = in@Wr+br --------------------
// v2 packing: accumulators are (row, column-pair) f32x2; A scalars packed once
// per row per k; weight PAIRS loaded directly from smem as 64-bit words.
// Removes 12 PACK2 movs per k-iteration (36 -> 26 instr).
__global__ void __launch_bounds__(256) k_gemm_dual(
        const float* __restrict__ x,
        const float* __restrict__ Wl, const float* __restrict__ bl,
        const float* __restrict__ Wr, const float* __restrict__ br,
        float* __restrict__ xl, float* __restrict__ xr) {
    __shared__ float sX[64 * 64];
    __shared__ float sWl[64 * 64];
    __shared__ float sWr[64 * 64];
    int tid = threadIdx.x;
    int row0 = blockIdx.x * 64;
    for (int i = tid; i < 1024; i += 256) {
        ((float4*)sWl)[i] = ((const float4*)Wl)[i];
        ((float4*)sWr)[i] = ((const float4*)Wr)[i];
    }
    for (int i = tid; i < 1024; i += 256) {
        int r = i >> 4, k4 = (i & 15) << 2;
        float4 v = make_float4(0.f, 0.f, 0.f, 0.f);
        if (row0 + r < NN) v = *(const float4*)(x + (size_t)(row0 + r) * 64 + k4);
        *(float4*)(sX + r * 64 + k4) = v;
    }
    __syncthreads();
    int tx = tid & 15, ty = tid >> 4;
    int r0 = ty * 4, c0 = tx * 4;
    float4 bl4 = *(const float4*)(bl + c0);
    float4 br4 = *(const float4*)(br + c0);
    // acc[row][pair]: pair 0 = cols (c0,c0+1), pair 1 = cols (c0+2,c0+3)
    unsigned long long accl[4][2], accr[4][2];
    {
        unsigned long long l0, l1, r0p, r1p;
        PACK2(l0, bl4.x, bl4.y); PACK2(l1, bl4.z, bl4.w);
        PACK2(r0p, br4.x, br4.y); PACK2(r1p, br4.z, br4.w);
#pragma unroll
        for (int r = 0; r < 4; r++) {
            accl[r][0] = l0; accl[r][1] = l1;
            accr[r][0] = r0p; accr[r][1] = r1p;
        }
    }
#pragma unroll 4
    for (int k = 0; k < 64; k++) {
        float a0 = sX[(r0 + 0) * 64 + k];
        float a1 = sX[(r0 + 1) * 64 + k];
        float a2 = sX[(r0 + 2) * 64 + k];
        float a3 = sX[(r0 + 3) * 64 + k];
        unsigned long long pa0, pa1, pa2, pa3;
        PACK2(pa0, a0, a0); PACK2(pa1, a1, a1);
        PACK2(pa2, a2, a2); PACK2(pa3, a3, a3);
        ulonglong2 wl2 = *(const ulonglong2*)(sWl + k * 64 + c0);
        ulonglong2 wr2 = *(const ulonglong2*)(sWr + k * 64 + c0);
        FMA2(accl[0][0], pa0, wl2.x); FMA2(accl[0][1], pa0, wl2.y);
        FMA2(accl[1][0], pa1, wl2.x); FMA2(accl[1][1], pa1, wl2.y);
        FMA2(accl[2][0], pa2, wl2.x); FMA2(accl[2][1], pa2, wl2.y);
        FMA2(accl[3][0], pa3, wl2.x); FMA2(accl[3][1], pa3, wl2.y);
        FMA2(accr[0][0], pa0, wr2.x); FMA2(accr[0][1], pa0, wr2.y);
        FMA2(accr[1][0], pa1, wr2.x); FMA2(accr[1][1], pa1, wr2.y);
        FMA2(accr[2][0], pa2, wr2.x); FMA2(accr[2][1], pa2, wr2.y);
        FMA2(accr[3][0], pa3, wr2.x); FMA2(accr[3][1], pa3, wr2.y);
    }
#pragma unroll
    for (int r = 0; r < 4; r++) {
        int row = row0 + r0 + r;
        if (row < NN) {
            float4 vl, vr;
            UNPACK2(vl.x, vl.y, accl[r][0]); UNPACK2(vl.z, vl.w, accl[r][1]);
            UNPACK2(vr.x, vr.y, accr[r][0]); UNPACK2(vr.z, vr.w, accr[r][1]);
            *(float4*)(xl + (size_t)row * 64 + c0) = vl;
            *(float4*)(xr + (size_t)row * 64 + c0) = vr;
        }
    }
}

// ---------------- fused GATv2 edge phase --------------------------------------
// one node per 32-thread block (R12 config — best measured; prefetch variant
// R14 traded mem stalls for ALU issue, net neutral -> reverted).
// 2 groups of 16 lanes; each lane owns 4 features; 4 edge slots in flight per
// group; branch-free softmax; abs-trick scoring.
__global__ void __launch_bounds__(32) k_gat_node(
        const float* __restrict__ att, const float* __restrict__ bias,
        float* __restrict__ hout) {
    int n = blockIdx.x;
    int lane = threadIdx.x;
    int end = g_deg[n]; if (end > SLOT) end = SLOT;
    const int* srcs = g_slot + (size_t)n * SLOT;
    int sub = lane & 15;      // feature quad: features sub*4 .. sub*4+3
    int grp = lane >> 4;      // edge group 0..1

    float4 xr4 = *(const float4*)(g_xr + (size_t)n * 64 + sub * 4);
    float4 c2  = *(const float4*)(att + sub * 4);
    c2.x *= 0.4f; c2.y *= 0.4f; c2.z *= 0.4f; c2.w *= 0.4f;

    float den = 0.0f;
    float4 acc = make_float4(0.f, 0.f, 0.f, 0.f);

    for (int base = 0; base < end; base += 32) {
        int cnt = end - base; if (cnt > 32) cnt = 32;
        int sv = (base + lane < end) ? srcs[base + lane] : 0;
        for (int j = 0; j < cnt; j += 8) {
            int e0 = j + grp, e1 = j + 2 + grp, e2 = j + 4 + grp, e3 = j + 6 + grp;
            int s0 = __shfl_sync(0xffffffffu, sv, e0);
            int s1 = __shfl_sync(0xffffffffu, sv, e1);
            int s2 = __shfl_sync(0xffffffffu, sv, e2);
            int s3 = __shfl_sync(0xffffffffu, sv, e3);
            float4 a = *(const float4*)(g_xl + (size_t)s0 * 64 + sub * 4);
            float4 b = *(const float4*)(g_xl + (size_t)s1 * 64 + sub * 4);
            float4 c = *(const float4*)(g_xl + (size_t)s2 * 64 + sub * 4);
            float4 d = *(const float4*)(g_xl + (size_t)s3 * 64 + sub * 4);
            float p0 = 0.f, p1 = 0.f, p2 = 0.f, p3 = 0.f;
            p0 = scoreterm(a.x, xr4.x, c2.x, p0);
            p0 = scoreterm(a.y, xr4.y, c2.y, p0);
            p0 = scoreterm(a.z, xr4.z, c2.z, p0);
            p0 = scoreterm(a.w, xr4.w, c2.w, p0);
            p1 = scoreterm(b.x, xr4.x, c2.x, p1);
            p1 = scoreterm(b.y, xr4.y, c2.y, p1);
            p1 = scoreterm(b.z, xr4.z, c2.z, p1);
            p1 = scoreterm(b.w, xr4.w, c2.w, p1);
            p2 = scoreterm(c.x, xr4.x, c2.x, p2);
            p2 = scoreterm(c.y, xr4.y, c2.y, p2);
            p2 = scoreterm(c.z, xr4.z, c2.z, p2);
            p2 = scoreterm(c.w, xr4.w, c2.w, p2);
            p3 = scoreterm(d.x, xr4.x, c2.x, p3);
            p3 = scoreterm(d.y, xr4.y, c2.y, p3);
            p3 = scoreterm(d.z, xr4.z, c2.z, p3);
            p3 = scoreterm(d.w, xr4.w, c2.w, p3);
            // reduce over the 16-lane group
            p0 += __shfl_xor_sync(0xffffffffu, p0, 1);
            p1 += __shfl_xor_sync(0xffffffffu, p1, 1);
            p2 += __shfl_xor_sync(0xffffffffu, p2, 1);
            p3 += __shfl_xor_sync(0xffffffffu, p3, 1);
            p0 += __shfl_xor_sync(0xffffffffu, p0, 2);
            p1 += __shfl_xor_sync(0xffffffffu, p1, 2);
            p2 += __shfl_xor_sync(0xffffffffu, p2, 2);
            p3 += __shfl_xor_sync(0xffffffffu, p3, 2);
            p0 += __shfl_xor_sync(0xffffffffu, p0, 4);
            p1 += __shfl_xor_sync(0xffffffffu, p1, 4);
            p2 += __shfl_xor_sync(0xffffffffu, p2, 4);
            p3 += __shfl_xor_sync(0xffffffffu, p3, 4);
            p0 += __shfl_xor_sync(0xffffffffu, p0, 8);
            p1 += __shfl_xor_sync(0xffffffffu, p1, 8);
            p2 += __shfl_xor_sync(0xffffffffu, p2, 8);
            p3 += __shfl_xor_sync(0xffffffffu, p3, 8);
            if (e0 >= cnt) p0 = -1e30f;
            if (e1 >= cnt) p1 = -1e30f;
            if (e2 >= cnt) p2 = -1e30f;
            if (e3 >= cnt) p3 = -1e30f;
            float w0 = __expf(p0);
            float w1 = __expf(p1);
            float w2 = __expf(p2);
            float w3 = __expf(p3);
            den += (w0 + w1) + (w2 + w3);
            acc.x += w0 * a.x + w1 * b.x + w2 * c.x + w3 * d.x;
            acc.y += w0 * a.y + w1 * b.y + w2 * c.y + w3 * d.y;
            acc.z += w0 * a.z + w1 * b.z + w2 * c.z + w3 * d.z;
            acc.w += w0 * a.w + w1 * b.w + w2 * c.w + w3 * d.w;
        }
    }

    // merge the 2 group partial sums (plain adds)
    den   += __shfl_xor_sync(0xffffffffu, den, 16);
    acc.x += __shfl_xor_sync(0xffffffffu, acc.x, 16);
    acc.y += __shfl_xor_sync(0xffffffffu, acc.y, 16);
    acc.z += __shfl_xor_sync(0xffffffffu, acc.z, 16);
    acc.w += __shfl_xor_sync(0xffffffffu, acc.w, 16);

    if (grp == 0) {
        float inv = den > 0.0f ? 1.0f / den : 0.0f;
        float4 b4 = *(const float4*)(bias + sub * 4);
        float4 o;
        o.x = fmaxf(acc.x * inv + b4.x, 0.f);
        o.y = fmaxf(acc.y * inv + b4.y, 0.f);
        o.z = fmaxf(acc.z * inv + b4.z, 0.f);
        o.w = fmaxf(acc.w * inv + b4.w, 0.f);
        *(float4*)(hout + (size_t)n * 64 + sub * 4) = o;
    }
}

// ---------------- fused mean-pool + final linear -----------------------------
__global__ void __launch_bounds__(256) k_pool_final(
        const void* __restrict__ batch,
        const float* __restrict__ lw, const float* __restrict__ lb,
        float* __restrict__ out) {
    __shared__ float sp[8][64];
    int warp = (blockIdx.x << 3) + (threadIdx.x >> 5);
    int lane = threadIdx.x & 31;
    int wloc = threadIdx.x >> 5;
    if (warp >= GG) return;
    int g = warp;
    int b64 = g_b64;

    int lo = 0, hi = NN;
    while (lo < hi) { int mid = (lo + hi) >> 1; if (load_idx(batch, mid, b64) < (long long)g) lo = mid + 1; else hi = mid; }
    int beg = lo;
    hi = NN;
    while (lo < hi) { int mid = (lo + hi) >> 1; if (load_idx(batch, mid, b64) < (long long)(g + 1)) lo = mid + 1; else hi = mid; }
    int end = lo;

    float sx = 0.f, sy = 0.f;
    const float* hp = g_h + 2 * lane;
    int n = beg;
    for (; n + 4 <= end; n += 4) {
        float2 v0 = *(const float2*)(hp + (size_t)n * 64);
        float2 v1 = *(const float2*)(hp + (size_t)(n + 1) * 64);
        float2 v2 = *(const float2*)(hp + (size_t)(n + 2) * 64);
        float2 v3 = *(const float2*)(hp + (size_t)(n + 3) * 64);
        sx += (v0.x + v1.x) + (v2.x + v3.x);
        sy += (v0.y + v1.y) + (v2.y + v3.y);
    }
    for (; n < end; n++) {
        float2 v = *(const float2*)(hp + (size_t)n * 64);
        sx += v.x; sy += v.y;
    }
    float c = (float)(end - beg);
    c = c > 1.0f ? c : 1.0f;
    sp[wloc][2 * lane]     = sx / c;
    sp[wloc][2 * lane + 1] = sy / c;
    __syncwarp();
    float acc = lb[lane];
#pragma unroll
    for (int hh = 0; hh < 64; hh++) acc = fmaf(sp[wloc][hh], lw[hh * 32 + lane], acc);
    out[g * 32 + lane] = acc;
}

// ---------------- launch ---------------------------------------------------------
extern "C" void kernel_launch(void* const* d_in, const int* in_sizes, int n_in,
                              void* d_out, int out_size) {
    const float* x      = (const float*)d_in[0];
    const void*  ei     = d_in[1];
    const void*  batch  = d_in[2];
    const float* Wl1    = (const float*)d_in[3];
    const float* bl1    = (const float*)d_in[4];
    const float* Wr1    = (const float*)d_in[5];
    const float* br1    = (const float*)d_in[6];
    const float* att1   = (const float*)d_in[7];
    const float* bias1  = (const float*)d_in[8];
    const float* Wl2    = (const float*)d_in[9];
    const float* bl2    = (const float*)d_in[10];
    const float* Wr2    = (const float*)d_in[11];
    const float* br2    = (const float*)d_in[12];
    const float* att2   = (const float*)d_in[13];
    const float* bias2  = (const float*)d_in[14];
    const float* lin_w  = (const float*)d_in[15];
    const float* lin_b  = (const float*)d_in[16];

    float* xl = nullptr; float* xr = nullptr; float* h = nullptr;
    cudaGetSymbolAddress((void**)&xl, g_xl);
    cudaGetSymbolAddress((void**)&xr, g_xr);
    cudaGetSymbolAddress((void**)&h,  g_h);

    // side stream + events for fork/join (created once, outside any capture)
    static cudaStream_t s2 = nullptr;
    static cudaEvent_t evFork = nullptr, evJoin = nullptr;
    if (s2 == nullptr) {
        cudaStreamCreateWithFlags(&s2, cudaStreamNonBlocking);
        cudaEventCreateWithFlags(&evFork, cudaEventDisableTiming);
        cudaEventCreateWithFlags(&evJoin, cudaEventDisableTiming);
    }

    const int TB = 256;
    const int gEdge = (EE + TB - 1) / TB;         // 3125
    const int gNode = (NN + TB - 1) / TB;         // 196
    const int gGemm = (NN + 63) / 64;             // 782

    // fork: gemm1 on s2 runs concurrently with CSR build on the main stream
    cudaEventRecord(evFork, 0);
    cudaStreamWaitEvent(s2, evFork, 0);
    k_gemm_dual<<<gGemm, TB, 0, s2>>>(x, Wl1, bl1, Wr1, br1, xl, xr);
    cudaEventRecord(evJoin, s2);

    // one-pass padded CSR build on the main stream
    k_detect<<<gNode, TB>>>(ei, batch);
    k_build<<<gEdge, TB>>>(ei);

    // join: gat1 needs both CSR and gemm1 results
    cudaStreamWaitEvent(0, evJoin, 0);

    // ---- layer 1 ---- (one node per 32-thread block)
    k_gat_node<<<NN, 32>>>(att1, bias1, h);

    // ---- layer 2 ----
    k_gemm_dual<<<gGemm, TB>>>(h, Wl2, bl2, Wr2, br2, xl, xr);
    k_gat_node<<<NN, 32>>>(att2, bias2, h);

    // ---- fused pool + final linear ----
    k_pool_final<<<(GG + 7) / 8, TB>>>(batch, lin_w, lin_b, (float*)d_out);
}